// round 12
// baseline (speedup 1.0000x reference)
#include <cuda_runtime.h>

#define B_ 8192
#define T_ 128
#define DT_ 0.01f
#define WARPS 4
#define THREADS 128
#define ROWS_PER_BLOCK 16
#define NBLK (B_ / ROWS_PER_BLOCK)

// shared memory layout (float offsets)
// W1s rows: 0..17 dynamic (e6, ed6, xi6); 18 = beta (xE); 19 = gamma (xnu); 20 = alpha
#define OFF_W1   0        // [21][512]
#define OFF_WEN2 10752    // [256]
#define OFF_WD2T 11008    // [6][256] (transposed Wd2)
#define OFF_XB   12544    // [4 warps][20 k][4 rows x dup2]  (warp-private input tiles)
#define SMEM_FLOATS 13184
#define SMEM_BYTES (SMEM_FLOATS * 4)

typedef unsigned long long u64;

__device__ __forceinline__ u64 ffma2(u64 a, u64 b, u64 c) {
    u64 d; asm("fma.rn.f32x2 %0, %1, %2, %3;" : "=l"(d) : "l"(a), "l"(b), "l"(c));
    return d;
}
__device__ __forceinline__ u64 dup2(float x) {
    u64 d; asm("mov.b64 %0, {%1, %1};" : "=l"(d) : "f"(x));
    return d;
}
__device__ __forceinline__ float2 unpk(u64 a) {
    float2 r; asm("mov.b64 {%0, %1}, %2;" : "=f"(r.x), "=f"(r.y) : "l"(a));
    return r;
}
__device__ __forceinline__ u64 pk2(float x, float y) {
    u64 d; asm("mov.b64 %0, {%1, %2};" : "=l"(d) : "f"(x), "f"(y));
    return d;
}
__device__ __forceinline__ u64 relu2(u64 a) {
    float2 v = unpk(a);
    return pk2(fmaxf(v.x, 0.f), fmaxf(v.y, 0.f));
}

__global__ void __launch_bounds__(THREADS, 3) visco_kernel(
    const float* __restrict__ e_,   const float* __restrict__ ed_,
    const float* __restrict__ E_,   const float* __restrict__ nu_,
    const float* __restrict__ We,   const float* __restrict__ be,
    const float* __restrict__ Wn,   const float* __restrict__ bn,
    const float* __restrict__ Wen1, const float* __restrict__ ben1,
    const float* __restrict__ Wen2, const float* __restrict__ ben2,
    const float* __restrict__ Wd1,  const float* __restrict__ bd1,
    const float* __restrict__ Wd2,  const float* __restrict__ bd2,
    float* __restrict__ out)
{
    extern __shared__ float sm[];
    float* W1s   = sm + OFF_W1;
    float* Wen2s = sm + OFF_WEN2;
    float* Wd2t  = sm + OFF_WD2T;

    const int tid  = threadIdx.x;
    const int lane = tid & 31;
    const int warp = tid >> 5;

    float* xbW = sm + OFF_XB + warp * 160;   // [20][8] floats, warp-private

    // ---- cooperative smem fill: dynamic W1 rows 0..17 + layer-2 weights ----
    for (int i = tid; i < 18 * 512; i += THREADS) {
        int k = i >> 9, h = i & 511;
        W1s[i] = (h < 256) ? Wen1[k * 256 + h] : Wd1[k * 256 + (h - 256)];
    }
    for (int i = tid; i < 256; i += THREADS) Wen2s[i] = Wen2[i];
    for (int i = tid; i < 6 * 256; i += THREADS) {
        int j = i >> 8, h = i & 255;
        Wd2t[i] = Wd2[h * 6 + j];   // transpose -> conflict-free float4 reads
    }

    // ---- rows 18..20: beta = We@W1mf, gamma = Wn@W1mf, alpha = bias fold ----
    // mf = [E*We+be, nu*Wn+bn]  =>  c[h] = alpha[h] + E*beta[h] + nu*gamma[h]
    {
        const int h0 = 4 * tid;
        const float* bsrc = (h0 < 256) ? (ben1 + h0) : (bd1 + h0 - 256);
        const float* Wb   = (h0 < 256) ? (Wen1 + 18 * 256 + h0)
                                       : (Wd1  + 18 * 256 + h0 - 256);
        float al[4], bt[4], gm[4];
        #pragma unroll
        for (int el = 0; el < 4; el++) { al[el] = bsrc[el]; bt[el] = 0.f; gm[el] = 0.f; }
        for (int i = 0; i < 16; i++) {
            float4 wa = *(const float4*)(Wb + i * 256);          // W1 row 18+i (E-encoder)
            float4 wb = *(const float4*)(Wb + (16 + i) * 256);   // W1 row 34+i (nu-encoder)
            float wev = We[i], bev = be[i], wnv = Wn[i], bnv = bn[i];
            bt[0] = fmaf(wev, wa.x, bt[0]); bt[1] = fmaf(wev, wa.y, bt[1]);
            bt[2] = fmaf(wev, wa.z, bt[2]); bt[3] = fmaf(wev, wa.w, bt[3]);
            gm[0] = fmaf(wnv, wb.x, gm[0]); gm[1] = fmaf(wnv, wb.y, gm[1]);
            gm[2] = fmaf(wnv, wb.z, gm[2]); gm[3] = fmaf(wnv, wb.w, gm[3]);
            al[0] = fmaf(bev, wa.x, al[0]); al[1] = fmaf(bev, wa.y, al[1]);
            al[2] = fmaf(bev, wa.z, al[2]); al[3] = fmaf(bev, wa.w, al[3]);
            al[0] = fmaf(bnv, wb.x, al[0]); al[1] = fmaf(bnv, wb.y, al[1]);
            al[2] = fmaf(bnv, wb.z, al[2]); al[3] = fmaf(bnv, wb.w, al[3]);
        }
        *(float4*)(W1s + 18 * 512 + h0) = make_float4(bt[0], bt[1], bt[2], bt[3]);
        *(float4*)(W1s + 19 * 512 + h0) = make_float4(gm[0], gm[1], gm[2], gm[3]);
        *(float4*)(W1s + 20 * 512 + h0) = make_float4(al[0], al[1], al[2], al[3]);
    }

    const int gw   = blockIdx.x * WARPS + warp;
    const int row0 = gw * 4;

    // ---- distributed state: lane i = r*8+j owns output slot (r, j) ----
    const int jown = lane & 7;
    const int rown = lane >> 3;
    const float bd2v  = (jown < 6) ? bd2[jown] : 0.f;
    const float ben2r = ben2[0];
    float xi_val = 0.f;

    float* xi_ptr = out + B_ * T_ + ((row0 + rown) * T_) * 6 + jown;   // + t*6
    float* s_ptr  = out + (row0 + rown) * T_;                          // + t

    // lane -> (rowpair, input-dim) mapping for the per-step e/edot gather
    const int l2  = lane & 15;                // also the k index (0..11) for stagers
    const bool ldp = (l2 < 12);
    const float* lsrc = (l2 < 6) ? e_ : ed_;
    const int d_l = (l2 < 6) ? l2 : (l2 - 6);
    const int rA = row0 + ((lane < 16) ? 0 : 1);   // source rows for stream 0
    const int rB = row0 + ((lane < 16) ? 2 : 3);   // source rows for stream 1
    const int base0 = rA * T_ * 6 + d_l;
    const int base1 = rB * T_ * 6 + d_l;
    // staging slots (float offsets in xbW): xb[k = l2][row * 2]  (k covers e then ed)
    const int sb0 = l2 * 8 + ((lane < 16) ? 0 : 1) * 2;
    const int sb1 = l2 * 8 + ((lane < 16) ? 2 : 3) * 2;

    const float* W1w   = W1s + 4 * lane;            // + k*512 + 128*q
    const float* wen2w = Wen2s + 4 * lane;          // + 128*q
    const float* wd2w  = Wd2t + 4 * lane;           // + j*256 + 128*q

    // ---- initial staging: e/ed(t=0), xi=0, E/nu (static rows 18,19) ----
    if (ldp) {
        *(u64*)(xbW + sb0) = dup2(lsrc[base0]);
        *(u64*)(xbW + sb1) = dup2(lsrc[base1]);
    }
    if (jown < 6) *(u64*)(xbW + (12 + jown) * 8 + rown * 2) = 0ULL;
    if (lane < 4)      *(u64*)(xbW + 18 * 8 + lane * 2)       = dup2(E_[row0 + lane]);
    else if (lane < 8) *(u64*)(xbW + 19 * 8 + (lane - 4) * 2) = dup2(nu_[row0 + lane - 4]);

    __syncthreads();

    // prefetch e/ed for t=1
    float nxt0 = 0.f, nxt1 = 0.f;
    if (ldp) { nxt0 = lsrc[base0 + 6]; nxt1 = lsrc[base1 + 6]; }

    for (int t = 0; t < T_; t++) {
        __syncwarp();   // order prior cross-lane xb stores before this step's reads

        // issue LDG prefetch for t+2 early (latency hidden under k-loop)
        float pn0 = 0.f, pn1 = 0.f;
        {
            int tn = (t + 2 < T_) ? (t + 2) : (T_ - 1);
            if (ldp) { pn0 = lsrc[base0 + tn * 6]; pn1 = lsrc[base1 + tn * 6]; }
        }

        // ---- init accumulators from shared alpha row (broadcast across rows) ----
        u64 u2[4][4][2];   // [row][q][pair]
        #pragma unroll
        for (int q = 0; q < 4; q++) {
            ulonglong2 a = *(const ulonglong2*)(W1w + 20 * 512 + 128 * q);
            #pragma unroll
            for (int r = 0; r < 4; r++) { u2[r][q][0] = a.x; u2[r][q][1] = a.y; }
        }

        // ---- layer 1: 20 inputs x 512 hidden; inputs via broadcast LDS ----
        #pragma unroll
        for (int k = 0; k < 20; k++) {
            ulonglong2 x01 = *(const ulonglong2*)(xbW + k * 8);      // rows 0,1 (dup2)
            ulonglong2 x23 = *(const ulonglong2*)(xbW + k * 8 + 4);  // rows 2,3 (dup2)
            #pragma unroll
            for (int q = 0; q < 4; q++) {
                ulonglong2 w = *(const ulonglong2*)(W1w + k * 512 + 128 * q);
                u2[0][q][0] = ffma2(x01.x, w.x, u2[0][q][0]);
                u2[0][q][1] = ffma2(x01.x, w.y, u2[0][q][1]);
                u2[1][q][0] = ffma2(x01.y, w.x, u2[1][q][0]);
                u2[1][q][1] = ffma2(x01.y, w.y, u2[1][q][1]);
                u2[2][q][0] = ffma2(x23.x, w.x, u2[2][q][0]);
                u2[2][q][1] = ffma2(x23.x, w.y, u2[2][q][1]);
                u2[3][q][0] = ffma2(x23.y, w.x, u2[3][q][0]);
                u2[3][q][1] = ffma2(x23.y, w.y, u2[3][q][1]);
            }
        }

        __syncwarp();   // k-loop reads done in all lanes before overwriting e/ed
        // stage e/ed(t+1)
        if (ldp) {
            *(u64*)(xbW + sb0) = dup2(nxt0);
            *(u64*)(xbW + sb1) = dup2(nxt1);
        }
        nxt0 = pn0; nxt1 = pn1;

        // relu
        #pragma unroll
        for (int q = 0; q < 4; q++)
            #pragma unroll
            for (int r = 0; r < 4; r++) {
                u2[r][q][0] = relu2(u2[r][q][0]);
                u2[r][q][1] = relu2(u2[r][q][1]);
            }

        // ---- layer-2 local partials into slot array v[32]; slot i = r*8+j ----
        float v[32];
        #pragma unroll
        for (int j = 0; j < 6; j++) {
            ulonglong2 w0 = *(const ulonglong2*)(wd2w + j * 256);
            ulonglong2 w1 = *(const ulonglong2*)(wd2w + j * 256 + 128);
            #pragma unroll
            for (int r = 0; r < 4; r++) {
                u64 a2 = ffma2(u2[r][2][0], w0.x, 0ULL);
                a2 = ffma2(u2[r][2][1], w0.y, a2);
                a2 = ffma2(u2[r][3][0], w1.x, a2);
                a2 = ffma2(u2[r][3][1], w1.y, a2);
                float2 q = unpk(a2);
                v[r * 8 + j] = q.x + q.y;
            }
        }
        {
            ulonglong2 w0 = *(const ulonglong2*)(wen2w);
            ulonglong2 w1 = *(const ulonglong2*)(wen2w + 128);
            #pragma unroll
            for (int r = 0; r < 4; r++) {
                u64 s2 = ffma2(u2[r][0][0], w0.x, 0ULL);
                s2 = ffma2(u2[r][0][1], w0.y, s2);
                s2 = ffma2(u2[r][1][0], w1.x, s2);
                s2 = ffma2(u2[r][1][1], w1.y, s2);
                float2 q = unpk(s2);
                v[r * 8 + 6] = q.x + q.y;
                v[r * 8 + 7] = 0.f;
            }
        }

        // ---- fold-distribute reduction: lane i ends with sum over lanes of v[i] ----
        #pragma unroll
        for (int lvl = 0; lvl < 5; lvl++) {
            const int off = 16 >> lvl;
            #pragma unroll
            for (int m = 0; m < (16 >> lvl); m++) {
                float send = (lane & off) ? v[m] : v[m + off];
                float recv = __shfl_xor_sync(0xffffffffu, send, off);
                float keep = (lane & off) ? v[m + off] : v[m];
                v[m] = keep + recv;
            }
        }

        // ---- outputs: xi BEFORE update (owners j<6), stress (j==6) ----
        if (jown < 6)       xi_ptr[t * 6] = xi_val;
        else if (jown == 6) s_ptr[t] = v[0] + ben2r;

        // explicit Euler update, then stage xi(t+1) for next step's k-loop
        xi_val = fmaf(DT_, v[0] + bd2v, xi_val);
        if (jown < 6) *(u64*)(xbW + (12 + jown) * 8 + rown * 2) = dup2(xi_val);
    }
}

extern "C" void kernel_launch(void* const* d_in, const int* in_sizes, int n_in,
                              void* d_out, int out_size) {
    (void)in_sizes; (void)n_in; (void)out_size;
    cudaFuncSetAttribute(visco_kernel,
                         cudaFuncAttributeMaxDynamicSharedMemorySize, SMEM_BYTES);
    visco_kernel<<<NBLK, THREADS, SMEM_BYTES>>>(
        (const float*)d_in[0],  (const float*)d_in[1],
        (const float*)d_in[2],  (const float*)d_in[3],
        (const float*)d_in[4],  (const float*)d_in[5],
        (const float*)d_in[6],  (const float*)d_in[7],
        (const float*)d_in[8],  (const float*)d_in[9],
        (const float*)d_in[10], (const float*)d_in[11],
        (const float*)d_in[12], (const float*)d_in[13],
        (const float*)d_in[14], (const float*)d_in[15],
        (float*)d_out);
}

// round 13
// speedup vs baseline: 1.0630x; 1.0630x over previous
#include <cuda_runtime.h>

#define B_ 8192
#define T_ 128
#define DT_ 0.01f
#define WARPS 4
#define THREADS 128
#define ROWS_PER_WARP 8
#define NBLK (B_ / (WARPS * ROWS_PER_WARP))   // 256

// shared memory layout (float offsets)
// W1s rows: 0..17 dynamic (e6, ed6, xi6); 18 = beta (xE); 19 = gamma (xnu); 20 = alpha
#define OFF_W1   0        // [21][512]
#define OFF_WEN2 10752    // [256]
#define OFF_WD2T 11008    // [6][256] (transposed Wd2)
#define SMEM_FLOATS 12544
#define SMEM_BYTES (SMEM_FLOATS * 4)

typedef unsigned long long u64;

__device__ __forceinline__ u64 ffma2(u64 a, u64 b, u64 c) {
    u64 d; asm("fma.rn.f32x2 %0, %1, %2, %3;" : "=l"(d) : "l"(a), "l"(b), "l"(c));
    return d;
}
__device__ __forceinline__ u64 dup2(float x) {
    u64 d; asm("mov.b64 %0, {%1, %1};" : "=l"(d) : "f"(x));
    return d;
}
__device__ __forceinline__ float2 unpk(u64 a) {
    float2 r; asm("mov.b64 {%0, %1}, %2;" : "=f"(r.x), "=f"(r.y) : "l"(a));
    return r;
}
__device__ __forceinline__ u64 pk2(float x, float y) {
    u64 d; asm("mov.b64 %0, {%1, %2};" : "=l"(d) : "f"(x), "f"(y));
    return d;
}
__device__ __forceinline__ u64 relu2(u64 a) {
    float2 v = unpk(a);
    return pk2(fmaxf(v.x, 0.f), fmaxf(v.y, 0.f));
}

// fold-distribute over 32 slots: lane i ends with full-warp sum of v[i] in v[0]
__device__ __forceinline__ void fold32(float* v, int lane) {
    #pragma unroll
    for (int lvl = 0; lvl < 5; lvl++) {
        const int off = 16 >> lvl;
        #pragma unroll
        for (int m = 0; m < (16 >> lvl); m++) {
            float send = (lane & off) ? v[m] : v[m + off];
            float recv = __shfl_xor_sync(0xffffffffu, send, off);
            float keep = (lane & off) ? v[m + off] : v[m];
            v[m] = keep + recv;
        }
    }
}

__global__ void __launch_bounds__(THREADS, 2) visco_kernel(
    const float* __restrict__ e_,   const float* __restrict__ ed_,
    const float* __restrict__ E_,   const float* __restrict__ nu_,
    const float* __restrict__ We,   const float* __restrict__ be,
    const float* __restrict__ Wn,   const float* __restrict__ bn,
    const float* __restrict__ Wen1, const float* __restrict__ ben1,
    const float* __restrict__ Wen2, const float* __restrict__ ben2,
    const float* __restrict__ Wd1,  const float* __restrict__ bd1,
    const float* __restrict__ Wd2,  const float* __restrict__ bd2,
    float* __restrict__ out)
{
    extern __shared__ float sm[];
    float* W1s   = sm + OFF_W1;
    float* Wen2s = sm + OFF_WEN2;
    float* Wd2t  = sm + OFF_WD2T;

    const int tid  = threadIdx.x;
    const int lane = tid & 31;
    const int warp = tid >> 5;

    // ---- cooperative smem fill: dynamic W1 rows 0..17 + layer-2 weights ----
    for (int i = tid; i < 18 * 512; i += THREADS) {
        int k = i >> 9, h = i & 511;
        W1s[i] = (h < 256) ? Wen1[k * 256 + h] : Wd1[k * 256 + (h - 256)];
    }
    for (int i = tid; i < 256; i += THREADS) Wen2s[i] = Wen2[i];
    for (int i = tid; i < 6 * 256; i += THREADS) {
        int j = i >> 8, h = i & 255;
        Wd2t[i] = Wd2[h * 6 + j];   // transpose -> conflict-free float4 reads
    }

    // ---- rows 18..20: beta = We@W1mf, gamma = Wn@W1mf, alpha = bias fold ----
    // mf = [E*We+be, nu*Wn+bn]  =>  c[h] = alpha[h] + E*beta[h] + nu*gamma[h]
    {
        const int h0 = 4 * tid;
        const float* bsrc = (h0 < 256) ? (ben1 + h0) : (bd1 + h0 - 256);
        const float* Wb   = (h0 < 256) ? (Wen1 + 18 * 256 + h0)
                                       : (Wd1  + 18 * 256 + h0 - 256);
        float al[4], bt[4], gm[4];
        #pragma unroll
        for (int el = 0; el < 4; el++) { al[el] = bsrc[el]; bt[el] = 0.f; gm[el] = 0.f; }
        for (int i = 0; i < 16; i++) {
            float4 wa = *(const float4*)(Wb + i * 256);          // W1 row 18+i (E-encoder)
            float4 wb = *(const float4*)(Wb + (16 + i) * 256);   // W1 row 34+i (nu-encoder)
            float wev = We[i], bev = be[i], wnv = Wn[i], bnv = bn[i];
            bt[0] = fmaf(wev, wa.x, bt[0]); bt[1] = fmaf(wev, wa.y, bt[1]);
            bt[2] = fmaf(wev, wa.z, bt[2]); bt[3] = fmaf(wev, wa.w, bt[3]);
            gm[0] = fmaf(wnv, wb.x, gm[0]); gm[1] = fmaf(wnv, wb.y, gm[1]);
            gm[2] = fmaf(wnv, wb.z, gm[2]); gm[3] = fmaf(wnv, wb.w, gm[3]);
            al[0] = fmaf(bev, wa.x, al[0]); al[1] = fmaf(bev, wa.y, al[1]);
            al[2] = fmaf(bev, wa.z, al[2]); al[3] = fmaf(bev, wa.w, al[3]);
            al[0] = fmaf(bnv, wb.x, al[0]); al[1] = fmaf(bnv, wb.y, al[1]);
            al[2] = fmaf(bnv, wb.z, al[2]); al[3] = fmaf(bnv, wb.w, al[3]);
        }
        *(float4*)(W1s + 18 * 512 + h0) = make_float4(bt[0], bt[1], bt[2], bt[3]);
        *(float4*)(W1s + 19 * 512 + h0) = make_float4(gm[0], gm[1], gm[2], gm[3]);
        *(float4*)(W1s + 20 * 512 + h0) = make_float4(al[0], al[1], al[2], al[3]);
    }

    const int gw   = blockIdx.x * WARPS + warp;
    const int row0 = gw * ROWS_PER_WARP;

    // ---- owner mapping: lane < 28: slot = ro*7 + jo serves rows ro (tree A) and ro+4 (tree B)
    const int jo = lane % 7;
    const int ro = lane / 7;
    const bool owner = (lane < 28);
    const float bd2v  = (owner && jo < 6) ? bd2[jo] : 0.f;
    const float ben2r = ben2[0];
    float xiv0 = 0.f, xiv1 = 0.f;

    const int rAo = row0 + ((ro < 4) ? ro : 3);       // clamp (lanes>=28 unused)
    float* xiA = out + B_ * T_ + (rAo * T_) * 6 + jo;
    float* xiB = out + B_ * T_ + ((rAo + 4) * T_) * 6 + jo;
    float* sA  = out + rAo * T_;
    float* sB  = out + (rAo + 4) * T_;

    // E/nu stream: lane<8 -> E of row lane; lane 8..15 -> nu of row lane-8
    float Enu = 0.f;
    if (lane < 8)       Enu = E_[row0 + lane];
    else if (lane < 16) Enu = nu_[row0 + lane - 8];

    // lane -> (row-pair, input-dim) for e/edot gather: 4 streams of 2 rows each
    const int l2  = lane & 15;
    const bool ldp = (l2 < 12);
    const float* lsrc = (l2 < 6) ? e_ : ed_;
    const int d_l = (l2 < 6) ? l2 : (l2 - 6);
    const int rofs = (lane < 16) ? 0 : 1;
    int base[4];
    #pragma unroll
    for (int s = 0; s < 4; s++) base[s] = (row0 + 2 * s + rofs) * T_ * 6 + d_l;

    const float* W1w   = W1s + 4 * lane;            // + k*512 + 128*q
    const float* wen2w = Wen2s + 4 * lane;          // + 128*q
    const float* wd2w  = Wd2t + 4 * lane;           // + j*256 + 128*q

    __syncthreads();

    float nxt[4] = {0.f, 0.f, 0.f, 0.f};
    if (ldp) {
        #pragma unroll
        for (int s = 0; s < 4; s++) nxt[s] = lsrc[base[s]];
    }

    for (int t = 0; t < T_; t++) {
        float ld[4];
        #pragma unroll
        for (int s = 0; s < 4; s++) ld[s] = nxt[s];
        {
            int tn = (t + 1 < T_) ? (t + 1) : (T_ - 1);
            if (ldp) {
                #pragma unroll
                for (int s = 0; s < 4; s++) nxt[s] = lsrc[base[s] + tn * 6];
            }
        }

        // ---- init accumulators from shared alpha row (broadcast across rows) ----
        u64 u2[8][4][2];   // [row][q][pair]
        #pragma unroll
        for (int q = 0; q < 4; q++) {
            ulonglong2 a = *(const ulonglong2*)(W1w + 20 * 512 + 128 * q);
            #pragma unroll
            for (int r = 0; r < 8; r++) { u2[r][q][0] = a.x; u2[r][q][1] = a.y; }
        }

        // ---- layer 1: 20 inputs x 512 hidden x 8 rows (W1 LDS shared by all 8) ----
        #pragma unroll
        for (int k = 0; k < 20; k++) {
            u64 xd[8];
            if (k < 12) {
                #pragma unroll
                for (int s = 0; s < 4; s++) {
                    xd[2*s]   = dup2(__shfl_sync(0xffffffffu, ld[s], k));
                    xd[2*s+1] = dup2(__shfl_sync(0xffffffffu, ld[s], 16 + k));
                }
            } else if (k < 18) {
                const int js = k - 12;   // xi_j of row r lives in lane r*7+js
                #pragma unroll
                for (int r = 0; r < 4; r++) {
                    xd[r]     = dup2(__shfl_sync(0xffffffffu, xiv0, r * 7 + js));
                    xd[4 + r] = dup2(__shfl_sync(0xffffffffu, xiv1, r * 7 + js));
                }
            } else if (k == 18) {
                #pragma unroll
                for (int r = 0; r < 8; r++)
                    xd[r] = dup2(__shfl_sync(0xffffffffu, Enu, r));
            } else {
                #pragma unroll
                for (int r = 0; r < 8; r++)
                    xd[r] = dup2(__shfl_sync(0xffffffffu, Enu, 8 + r));
            }
            #pragma unroll
            for (int q = 0; q < 4; q++) {
                ulonglong2 w = *(const ulonglong2*)(W1w + k * 512 + 128 * q);
                #pragma unroll
                for (int r = 0; r < 8; r++) {
                    u2[r][q][0] = ffma2(xd[r], w.x, u2[r][q][0]);
                    u2[r][q][1] = ffma2(xd[r], w.y, u2[r][q][1]);
                }
            }
        }

        // relu
        #pragma unroll
        for (int q = 0; q < 4; q++)
            #pragma unroll
            for (int r = 0; r < 8; r++) {
                u2[r][q][0] = relu2(u2[r][q][0]);
                u2[r][q][1] = relu2(u2[r][q][1]);
            }

        // ---- layer-2 partials: tree A (rows 0-3), tree B (rows 4-7); slot = r*7+j ----
        float vA[32], vB[32];
        #pragma unroll
        for (int j = 0; j < 6; j++) {
            ulonglong2 w0 = *(const ulonglong2*)(wd2w + j * 256);
            ulonglong2 w1 = *(const ulonglong2*)(wd2w + j * 256 + 128);
            #pragma unroll
            for (int r = 0; r < 4; r++) {
                u64 a2 = ffma2(u2[r][2][0], w0.x, 0ULL);
                a2 = ffma2(u2[r][2][1], w0.y, a2);
                a2 = ffma2(u2[r][3][0], w1.x, a2);
                a2 = ffma2(u2[r][3][1], w1.y, a2);
                float2 q = unpk(a2);
                vA[r * 7 + j] = q.x + q.y;
            }
            #pragma unroll
            for (int r = 4; r < 8; r++) {
                u64 a2 = ffma2(u2[r][2][0], w0.x, 0ULL);
                a2 = ffma2(u2[r][2][1], w0.y, a2);
                a2 = ffma2(u2[r][3][0], w1.x, a2);
                a2 = ffma2(u2[r][3][1], w1.y, a2);
                float2 q = unpk(a2);
                vB[(r - 4) * 7 + j] = q.x + q.y;
            }
        }
        {
            ulonglong2 w0 = *(const ulonglong2*)(wen2w);
            ulonglong2 w1 = *(const ulonglong2*)(wen2w + 128);
            #pragma unroll
            for (int r = 0; r < 4; r++) {
                u64 s2 = ffma2(u2[r][0][0], w0.x, 0ULL);
                s2 = ffma2(u2[r][0][1], w0.y, s2);
                s2 = ffma2(u2[r][1][0], w1.x, s2);
                s2 = ffma2(u2[r][1][1], w1.y, s2);
                float2 q = unpk(s2);
                vA[r * 7 + 6] = q.x + q.y;
            }
            #pragma unroll
            for (int r = 4; r < 8; r++) {
                u64 s2 = ffma2(u2[r][0][0], w0.x, 0ULL);
                s2 = ffma2(u2[r][0][1], w0.y, s2);
                s2 = ffma2(u2[r][1][0], w1.x, s2);
                s2 = ffma2(u2[r][1][1], w1.y, s2);
                float2 q = unpk(s2);
                vB[(r - 4) * 7 + 6] = q.x + q.y;
            }
        }
        #pragma unroll
        for (int m = 28; m < 32; m++) { vA[m] = 0.f; vB[m] = 0.f; }

        fold32(vA, lane);
        fold32(vB, lane);
        // lane i (<28) now owns: vA[0] = slot i of rows 0-3, vB[0] = slot i of rows 4-7

        // ---- outputs: xi BEFORE update; stress ----
        if (owner) {
            if (jo < 6) {
                xiA[t * 6] = xiv0;
                xiB[t * 6] = xiv1;
            } else {
                sA[t] = vA[0] + ben2r;
                sB[t] = vB[0] + ben2r;
            }
        }

        // explicit Euler update (garbage on non-owner lanes, never read)
        xiv0 = fmaf(DT_, vA[0] + bd2v, xiv0);
        xiv1 = fmaf(DT_, vB[0] + bd2v, xiv1);
    }
}

extern "C" void kernel_launch(void* const* d_in, const int* in_sizes, int n_in,
                              void* d_out, int out_size) {
    (void)in_sizes; (void)n_in; (void)out_size;
    cudaFuncSetAttribute(visco_kernel,
                         cudaFuncAttributeMaxDynamicSharedMemorySize, SMEM_BYTES);
    visco_kernel<<<NBLK, THREADS, SMEM_BYTES>>>(
        (const float*)d_in[0],  (const float*)d_in[1],
        (const float*)d_in[2],  (const float*)d_in[3],
        (const float*)d_in[4],  (const float*)d_in[5],
        (const float*)d_in[6],  (const float*)d_in[7],
        (const float*)d_in[8],  (const float*)d_in[9],
        (const float*)d_in[10], (const float*)d_in[11],
        (const float*)d_in[12], (const float*)d_in[13],
        (const float*)d_in[14], (const float*)d_in[15],
        (float*)d_out);
}